// round 17
// baseline (speedup 1.0000x reference)
#include <cuda_runtime.h>
#include <cuda_bf16.h>
#include <cstdint>

// ---------------- problem constants ----------------
#define N_NODES   100000
#define N_EDGES   1600000
#define NUM_GRAPHS 1024
#define IN_FEAT   7
#define H         128
#define BN_EPS    1e-5f

#define LDP 132        // padded stride for l0 kernel (R9-proven)
#define CHUNK 1024
#define NCHUNK ((N_NODES + CHUNK - 1) / CHUNK)   // 98

typedef unsigned long long ull;

// ---------------- scratch (device globals, no allocation) ----------------
__device__ __align__(256) float g_agg7[(size_t)N_NODES * 8];
__device__ __align__(256) float g_cat[(size_t)N_NODES * 3 * H];
__device__ __align__(256) float g_pool[(size_t)NUM_GRAPHS * 3 * H];
__device__ __align__(256) float g_hid[(size_t)NUM_GRAPHS * 2 * H];
// CSR-by-dst build
__device__ int g_deg[N_NODES];
__device__ int g_cursor[N_NODES];
__device__ int g_rowstart[N_NODES + 1];
__device__ int g_esrc[N_EDGES];
__device__ int g_chunkoff[NCHUNK];

// ---------------- helpers ----------------
__device__ __forceinline__ void ffma2(ull& d, ull a, ull b) {
    asm("fma.rn.f32x2 %0, %1, %2, %0;" : "+l"(d) : "l"(a), "l"(b));
}
__device__ __forceinline__ ull pkdup(float a) {
    ull r; asm("mov.b64 %0, {%1, %1};" : "=l"(r) : "f"(a)); return r;
}
__device__ __forceinline__ float2 unpk(ull v) {
    float2 r; asm("mov.b64 {%0, %1}, %2;" : "=f"(r.x), "=f"(r.y) : "l"(v)); return r;
}
__device__ __forceinline__ void red_add_v4(float* addr, float4 v) {
    asm volatile("red.global.add.v4.f32 [%0], {%1, %2, %3, %4};"
                 :: "l"(addr), "f"(v.x), "f"(v.y), "f"(v.z), "f"(v.w)
                 : "memory");
}
__device__ __forceinline__ float f4c(const float4& v, int k) {
    return (k == 0) ? v.x : (k == 1) ? v.y : (k == 2) ? v.z : v.w;
}
__device__ __forceinline__ uint32_t smem_to_u32(const void* p) {
    uint32_t a;
    asm("{ .reg .u64 t; cvta.to.shared.u64 t, %1; cvt.u32.u64 %0, t; }" : "=r"(a) : "l"(p));
    return a;
}
__device__ __forceinline__ void cpa16(uint32_t d, const float* s) {
    asm volatile("cp.async.cg.shared.global [%0], [%1], 16;" :: "r"(d), "l"(s));
}
#define CP_COMMIT() asm volatile("cp.async.commit_group;" ::: "memory")
#define CP_WAIT0()  asm volatile("cp.async.wait_group 0;" ::: "memory")

// ---------------- CSR build ----------------
__global__ void hist_kernel(const int* __restrict__ dst, int* __restrict__ deg, int E)
{
    int e = blockIdx.x * blockDim.x + threadIdx.x;
    if (e < E) atomicAdd(&deg[dst[e]], 1);
}

__global__ void scan1_kernel(const int* __restrict__ deg, int* __restrict__ chunkoff, int N)
{
    __shared__ int ss[256];
    int t = threadIdx.x;
    int base = blockIdx.x * CHUNK + t * 4;
    int s = 0;
    #pragma unroll
    for (int i = 0; i < 4; i++) { int idx = base + i; if (idx < N) s += deg[idx]; }
    ss[t] = s; __syncthreads();
    for (int off = 128; off > 0; off >>= 1) {
        if (t < off) ss[t] += ss[t + off];
        __syncthreads();
    }
    if (t == 0) chunkoff[blockIdx.x] = ss[0];
}

__global__ void scan2_kernel(int* __restrict__ chunkoff, int* __restrict__ rowstart,
                             int nchunk, int N)
{
    if (threadIdx.x == 0 && blockIdx.x == 0) {
        int run = 0;
        for (int i = 0; i < nchunk; i++) { int v = chunkoff[i]; chunkoff[i] = run; run += v; }
        rowstart[N] = run;    // == E
    }
}

__global__ void scan3_kernel(const int* __restrict__ deg, const int* __restrict__ chunkoff,
                             int* __restrict__ rowstart, int* __restrict__ cursor, int N)
{
    __shared__ int ss[256];
    int t = threadIdx.x;
    int base = blockIdx.x * CHUNK + t * 4;
    int v[4]; int s = 0;
    #pragma unroll
    for (int i = 0; i < 4; i++) { int idx = base + i; v[i] = (idx < N) ? deg[idx] : 0; s += v[i]; }
    ss[t] = s; __syncthreads();
    for (int off = 1; off < 256; off <<= 1) {
        int u = (t >= off) ? ss[t - off] : 0;
        __syncthreads();
        ss[t] += u;
        __syncthreads();
    }
    int excl = ss[t] - s + chunkoff[blockIdx.x];
    #pragma unroll
    for (int i = 0; i < 4; i++) {
        int idx = base + i;
        if (idx < N) { rowstart[idx] = excl; cursor[idx] = excl; excl += v[i]; }
    }
}

__global__ void fill_kernel(const int* __restrict__ src, const int* __restrict__ dst,
                            int* __restrict__ cursor, int* __restrict__ esrc, int E)
{
    int e = blockIdx.x * blockDim.x + threadIdx.x;
    if (e >= E) return;
    int p = atomicAdd(&cursor[dst[e]], 1);
    esrc[p] = src[e];
}

// ---------------- layer 0: scatter of 7-dim raw features ----------------
__global__ void scatter7_kernel(const float* __restrict__ x,
                                const int* __restrict__ src,
                                const int* __restrict__ dst,
                                float* __restrict__ agg, int E)
{
    int e = blockIdx.x * blockDim.x + threadIdx.x;
    if (e >= E) return;
    int s = src[e];
    int d = dst[e];
    const float* xr = x + (size_t)s * IN_FEAT;
    float* ar = agg + (size_t)d * 8;
    #pragma unroll
    for (int k = 0; k < IN_FEAT; k++) atomicAdd(ar + k, xr[k]);
}

// ---------------- fused GIN layer (layers 1,2): gather + 2 GEMMs --------------
// C = relu(relu((h[d] + sum_{s in N(d)} h[s]) @ B1 + b1) @ B2 + b2)
// One CTA = 128 nodes. Gather fills z_s (A, row-major); GEMM1 consumes it;
// epilogue 1 overwrites z_s with z; GEMM2 -> C. B tiles cp.async double-buffered.
// smem: z_s[128*128] | Bs0[16*128] | Bs1[16*128] = 81920 bytes, 2 CTAs/SM.
__global__ void __launch_bounds__(256, 2)
fused_gin_kernel(const float* __restrict__ h, int ldH,
                 const int* __restrict__ rowstart,
                 const int* __restrict__ esrc,
                 const float* __restrict__ B1, const float* __restrict__ b1,
                 const float* __restrict__ B2, const float* __restrict__ b2,
                 float* __restrict__ C, int ldC, int N)
{
    extern __shared__ float sm[];
    float* z_s = sm;                       // 128 x 128 (A, then z)
    float* Bs[2] = { sm + 16384, sm + 16384 + 2048 };

    int tid = threadIdx.x;
    int tx = tid & 15, ty = tid >> 4;
    int w = tid >> 5, lane = tid & 31;
    int m0 = blockIdx.x * 128;

    uint32_t sbase = smem_to_u32(sm);
    uint32_t bs_u[2] = { sbase + 16384 * 4, sbase + (16384 + 2048) * 4 };

    auto stageB = [&](const float* Bsrc, int t, int buf) {
        #pragma unroll
        for (int u = 0; u < 2; u++) {
            int i = tid + u * 256;
            int kr = i >> 5, c = i & 31;
            cpa16(bs_u[buf] + (uint32_t)(kr * 128 + c * 4) * 4,
                  Bsrc + (size_t)(t * 16 + kr) * H + c * 4);
        }
    };

    // prefetch B1 tile 0 while gathering
    stageB(B1, 0, 0); CP_COMMIT();

    // ---- gather phase: z_s[n][:] = h[node] + sum_{s} h[s] ----
    for (int n = w; n < 128; n += 8) {
        int node = m0 + n;
        float4 acc4 = make_float4(0.f, 0.f, 0.f, 0.f);
        if (node < N) {
            acc4 = *reinterpret_cast<const float4*>(h + (size_t)node * ldH + lane * 4);
            int beg = rowstart[node], end = rowstart[node + 1];
            int e = beg;
            for (; e + 4 <= end; e += 4) {
                int s0 = __ldg(esrc + e + 0);
                int s1 = __ldg(esrc + e + 1);
                int s2 = __ldg(esrc + e + 2);
                int s3 = __ldg(esrc + e + 3);
                float4 v0 = *reinterpret_cast<const float4*>(h + (size_t)s0 * ldH + lane * 4);
                float4 v1 = *reinterpret_cast<const float4*>(h + (size_t)s1 * ldH + lane * 4);
                float4 v2 = *reinterpret_cast<const float4*>(h + (size_t)s2 * ldH + lane * 4);
                float4 v3 = *reinterpret_cast<const float4*>(h + (size_t)s3 * ldH + lane * 4);
                acc4.x += v0.x + v1.x + v2.x + v3.x;
                acc4.y += v0.y + v1.y + v2.y + v3.y;
                acc4.z += v0.z + v1.z + v2.z + v3.z;
                acc4.w += v0.w + v1.w + v2.w + v3.w;
            }
            for (; e < end; e++) {
                int s = __ldg(esrc + e);
                float4 v = *reinterpret_cast<const float4*>(h + (size_t)s * ldH + lane * 4);
                acc4.x += v.x; acc4.y += v.y; acc4.z += v.z; acc4.w += v.w;
            }
        }
        *reinterpret_cast<float4*>(&z_s[n * 128 + lane * 4]) = acc4;
    }
    __syncthreads();

    // ---- phase 1: z = relu(A @ B1 + b1), A resident in z_s ----
    ull acc[8][4];
    #pragma unroll
    for (int i = 0; i < 8; i++)
        #pragma unroll
        for (int j = 0; j < 4; j++) acc[i][j] = 0ULL;

    #pragma unroll 1
    for (int t = 0; t < 8; t++) {
        CP_WAIT0();
        __syncthreads();
        if (t < 7) { stageB(B1, t + 1, (t + 1) & 1); CP_COMMIT(); }
        const float* Bc = Bs[t & 1];
        int kb = t * 16;
        #pragma unroll
        for (int kc = 0; kc < 16; kc += 4) {
            float4 rav[8];
            #pragma unroll
            for (int i = 0; i < 8; i++)
                rav[i] = *reinterpret_cast<const float4*>(&z_s[(ty * 8 + i) * 128 + kb + kc]);
            #pragma unroll
            for (int k4 = 0; k4 < 4; k4++) {
                int kr = kc + k4;
                ulonglong2 bp0 = *reinterpret_cast<const ulonglong2*>(&Bc[kr * 128 + tx * 4]);
                ulonglong2 bp1 = *reinterpret_cast<const ulonglong2*>(&Bc[kr * 128 + 64 + tx * 4]);
                ull bb[4] = {bp0.x, bp0.y, bp1.x, bp1.y};
                ull ad[8];
                #pragma unroll
                for (int i = 0; i < 8; i++) ad[i] = pkdup(f4c(rav[i], k4));
                #pragma unroll
                for (int i = 0; i < 8; i++)
                    #pragma unroll
                    for (int j = 0; j < 4; j++) ffma2(acc[i][j], ad[i], bb[j]);
            }
        }
    }

    // prefetch B2 tile 0 into Bs0 (t=7 compute used Bs1 — safe)
    stageB(B2, 0, 0); CP_COMMIT();
    __syncthreads();      // ALL warps done reading A before z_s is overwritten

    // epilogue 1: bias + relu -> z_s row-major
    #pragma unroll
    for (int i = 0; i < 8; i++) {
        int r = ty * 8 + i;
        #pragma unroll
        for (int hlf = 0; hlf < 2; hlf++) {
            int j0 = hlf * 64 + tx * 4;
            float2 p0 = unpk(acc[i][hlf * 2 + 0]);
            float2 p1 = unpk(acc[i][hlf * 2 + 1]);
            float4 o;
            o.x = fmaxf(p0.x + b1[j0 + 0], 0.f);
            o.y = fmaxf(p0.y + b1[j0 + 1], 0.f);
            o.z = fmaxf(p1.x + b1[j0 + 2], 0.f);
            o.w = fmaxf(p1.y + b1[j0 + 3], 0.f);
            *reinterpret_cast<float4*>(&z_s[r * 128 + j0]) = o;
        }
    }

    // ---- phase 2: C = relu(z @ B2 + b2) ----
    ull acc2[8][4];
    #pragma unroll
    for (int i = 0; i < 8; i++)
        #pragma unroll
        for (int j = 0; j < 4; j++) acc2[i][j] = 0ULL;

    #pragma unroll 1
    for (int t = 0; t < 8; t++) {
        CP_WAIT0();
        __syncthreads();              // first iter also publishes z_s
        if (t < 7) { stageB(B2, t + 1, (t + 1) & 1); CP_COMMIT(); }
        const float* Bc = Bs[t & 1];
        int kb = t * 16;
        #pragma unroll
        for (int kc = 0; kc < 16; kc += 4) {
            float4 rav[8];
            #pragma unroll
            for (int i = 0; i < 8; i++)
                rav[i] = *reinterpret_cast<const float4*>(&z_s[(ty * 8 + i) * 128 + kb + kc]);
            #pragma unroll
            for (int k4 = 0; k4 < 4; k4++) {
                int kr = kc + k4;
                ulonglong2 bp0 = *reinterpret_cast<const ulonglong2*>(&Bc[kr * 128 + tx * 4]);
                ulonglong2 bp1 = *reinterpret_cast<const ulonglong2*>(&Bc[kr * 128 + 64 + tx * 4]);
                ull bb[4] = {bp0.x, bp0.y, bp1.x, bp1.y};
                ull ad[8];
                #pragma unroll
                for (int i = 0; i < 8; i++) ad[i] = pkdup(f4c(rav[i], k4));
                #pragma unroll
                for (int i = 0; i < 8; i++)
                    #pragma unroll
                    for (int j = 0; j < 4; j++) ffma2(acc2[i][j], ad[i], bb[j]);
            }
        }
    }

    // epilogue 2: bias + relu -> C
    #pragma unroll
    for (int i = 0; i < 8; i++) {
        int gr = m0 + ty * 8 + i;
        if (gr < N) {
            #pragma unroll
            for (int hlf = 0; hlf < 2; hlf++) {
                int j0 = hlf * 64 + tx * 4;
                float2 p0 = unpk(acc2[i][hlf * 2 + 0]);
                float2 p1 = unpk(acc2[i][hlf * 2 + 1]);
                float4 o;
                o.x = fmaxf(p0.x + b2[j0 + 0], 0.f);
                o.y = fmaxf(p0.y + b2[j0 + 1], 0.f);
                o.z = fmaxf(p1.x + b2[j0 + 2], 0.f);
                o.w = fmaxf(p1.y + b2[j0 + 3], 0.f);
                *reinterpret_cast<float4*>(C + (size_t)gr * ldC + j0) = o;
            }
        }
    }
}

// ---------------- fused layer-0 MLP: K1 = 7 (R9-proven, unchanged) -----------
__global__ void __launch_bounds__(256, 2)
fused_l0_kernel(const float* __restrict__ x,
                const float* __restrict__ agg7,
                const float* __restrict__ B1, const float* __restrict__ b1,
                const float* __restrict__ B2, const float* __restrict__ b2,
                float* __restrict__ C, int ldC, int N)
{
    extern __shared__ float sm[];
    float* z_s  = sm;                     // 128 x LDP
    float* in_s = sm + 128 * LDP;         // 128 x 8
    float* Bs   = in_s + 1024;            // 16 x LDP

    int tid = threadIdx.x;
    int tx = tid & 15, ty = tid >> 4;
    int m0 = blockIdx.x * 128;

    for (int i = tid; i < 128 * IN_FEAT; i += 256) {
        int r = i / IN_FEAT, k = i % IN_FEAT;
        int gr = m0 + r;
        in_s[r * 8 + k] = (gr < N)
            ? x[(size_t)gr * IN_FEAT + k] + agg7[(size_t)gr * 8 + k] : 0.f;
    }
    for (int i = tid; i < IN_FEAT * H; i += 256) {
        int kr = i >> 7, c = i & 127;
        Bs[kr * LDP + c] = B1[i];
    }
    __syncthreads();

    ull acc[8][4];
    #pragma unroll
    for (int i = 0; i < 8; i++)
        #pragma unroll
        for (int j = 0; j < 4; j++) acc[i][j] = 0ULL;

    #pragma unroll
    for (int k = 0; k < IN_FEAT; k++) {
        ulonglong2 bp0 = *reinterpret_cast<const ulonglong2*>(&Bs[k * LDP + tx * 4]);
        ulonglong2 bp1 = *reinterpret_cast<const ulonglong2*>(&Bs[k * LDP + 64 + tx * 4]);
        ull bb[4] = {bp0.x, bp0.y, bp1.x, bp1.y};
        ull ad[8];
        #pragma unroll
        for (int i = 0; i < 8; i++) ad[i] = pkdup(in_s[(ty * 8 + i) * 8 + k]);
        #pragma unroll
        for (int i = 0; i < 8; i++)
            #pragma unroll
            for (int j = 0; j < 4; j++) ffma2(acc[i][j], ad[i], bb[j]);
    }

    #pragma unroll
    for (int i = 0; i < 8; i++) {
        int r = ty * 8 + i;
        #pragma unroll
        for (int hlf = 0; hlf < 2; hlf++) {
            int j0 = hlf * 64 + tx * 4;
            float2 p0 = unpk(acc[i][hlf * 2 + 0]);
            float2 p1 = unpk(acc[i][hlf * 2 + 1]);
            float4 o;
            o.x = fmaxf(p0.x + b1[j0 + 0], 0.f);
            o.y = fmaxf(p0.y + b1[j0 + 1], 0.f);
            o.z = fmaxf(p1.x + b1[j0 + 2], 0.f);
            o.w = fmaxf(p1.y + b1[j0 + 3], 0.f);
            *reinterpret_cast<float4*>(&z_s[r * LDP + j0]) = o;
        }
    }
    __syncthreads();

    ull acc2[8][4];
    #pragma unroll
    for (int i = 0; i < 8; i++)
        #pragma unroll
        for (int j = 0; j < 4; j++) acc2[i][j] = 0ULL;

    for (int kt = 0; kt < H; kt += 16) {
        #pragma unroll
        for (int u = 0; u < 2; u++) {
            int i = tid + u * 256;
            int kr = i >> 5;
            int c4 = (i & 31) * 4;
            *reinterpret_cast<float4*>(&Bs[kr * LDP + c4]) =
                *reinterpret_cast<const float4*>(B2 + (size_t)(kt + kr) * H + c4);
        }
        __syncthreads();
        #pragma unroll
        for (int kc = 0; kc < 16; kc += 4) {
            float4 rav[8];
            #pragma unroll
            for (int i = 0; i < 8; i++)
                rav[i] = *reinterpret_cast<const float4*>(&z_s[(ty * 8 + i) * LDP + kt + kc]);
            #pragma unroll
            for (int k4 = 0; k4 < 4; k4++) {
                int kr = kc + k4;
                ulonglong2 bp0 = *reinterpret_cast<const ulonglong2*>(&Bs[kr * LDP + tx * 4]);
                ulonglong2 bp1 = *reinterpret_cast<const ulonglong2*>(&Bs[kr * LDP + 64 + tx * 4]);
                ull bb[4] = {bp0.x, bp0.y, bp1.x, bp1.y};
                ull ad[8];
                #pragma unroll
                for (int i = 0; i < 8; i++) ad[i] = pkdup(f4c(rav[i], k4));
                #pragma unroll
                for (int i = 0; i < 8; i++)
                    #pragma unroll
                    for (int j = 0; j < 4; j++) ffma2(acc2[i][j], ad[i], bb[j]);
            }
        }
        __syncthreads();
    }

    #pragma unroll
    for (int i = 0; i < 8; i++) {
        int gr = m0 + ty * 8 + i;
        if (gr < N) {
            #pragma unroll
            for (int hlf = 0; hlf < 2; hlf++) {
                int j0 = hlf * 64 + tx * 4;
                float2 p0 = unpk(acc2[i][hlf * 2 + 0]);
                float2 p1 = unpk(acc2[i][hlf * 2 + 1]);
                float4 o;
                o.x = fmaxf(p0.x + b2[j0 + 0], 0.f);
                o.y = fmaxf(p0.y + b2[j0 + 1], 0.f);
                o.z = fmaxf(p1.x + b2[j0 + 2], 0.f);
                o.w = fmaxf(p1.y + b2[j0 + 3], 0.f);
                *reinterpret_cast<float4*>(C + (size_t)gr * ldC + j0) = o;
            }
        }
    }
}

// ---------------- global add pool over batch ids ----------------
__global__ void pool_kernel(const float* __restrict__ cat,
                            const int* __restrict__ batch,
                            float* __restrict__ pool, int N)
{
    int t = blockIdx.x * blockDim.x + threadIdx.x;
    int total = N * 96;
    if (t >= total) return;
    int n = t / 96;
    int q = t % 96;
    int g = batch[n];
    float4 v = reinterpret_cast<const float4*>(cat)[(size_t)n * 96 + q];
    red_add_v4(pool + (size_t)g * 384 + q * 4, v);
}

// ---------------- classifier layer 1: 384 -> 256 + BN + relu ----------------
__global__ void clf1_kernel(const float* __restrict__ pool,
                            const float* __restrict__ w,
                            const float* __restrict__ b,
                            const float* __restrict__ gamma,
                            const float* __restrict__ beta,
                            const float* __restrict__ mean,
                            const float* __restrict__ var,
                            float* __restrict__ hid)
{
    __shared__ float sp[384];
    int g = blockIdx.x;
    int j = threadIdx.x;                 // 256
    for (int i = j; i < 384; i += 256) sp[i] = pool[(size_t)g * 384 + i];
    __syncthreads();
    float acc = b[j];
    #pragma unroll 8
    for (int k = 0; k < 384; k++) acc += sp[k] * __ldg(w + (size_t)k * 256 + j);
    acc = (acc - mean[j]) * rsqrtf(var[j] + BN_EPS) * gamma[j] + beta[j];
    hid[(size_t)g * 256 + j] = fmaxf(acc, 0.f);
}

// ---------------- classifier layer 2: 256 -> 2 ----------------
__global__ void clf2_kernel(const float* __restrict__ hid,
                            const float* __restrict__ w,
                            const float* __restrict__ b,
                            float* __restrict__ out)
{
    int t = blockIdx.x * blockDim.x + threadIdx.x;
    if (t >= NUM_GRAPHS * 2) return;
    int g = t >> 1, j = t & 1;
    float acc = b[j];
    const float* hr = hid + (size_t)g * 256;
    #pragma unroll 8
    for (int k = 0; k < 256; k++) acc += hr[k] * __ldg(w + k * 2 + j);
    out[t] = acc;
}

// ---------------- launch ----------------
extern "C" void kernel_launch(void* const* d_in, const int* in_sizes, int n_in,
                              void* d_out, int out_size)
{
    const float* x      = (const float*)d_in[0];
    const int*   ei     = (const int*)d_in[1];
    const int*   batch  = (const int*)d_in[2];
    const float* w1[3], *b1[3], *w2[3], *b2[3];
    for (int l = 0; l < 3; l++) {
        w1[l] = (const float*)d_in[3 + 4 * l + 0];
        b1[l] = (const float*)d_in[3 + 4 * l + 1];
        w2[l] = (const float*)d_in[3 + 4 * l + 2];
        b2[l] = (const float*)d_in[3 + 4 * l + 3];
    }
    const float* clf_w1 = (const float*)d_in[15];
    const float* clf_b1 = (const float*)d_in[16];
    const float* clf_w2 = (const float*)d_in[17];
    const float* clf_b2 = (const float*)d_in[18];
    const float* bn_g   = (const float*)d_in[19];
    const float* bn_b   = (const float*)d_in[20];
    const float* bn_m   = (const float*)d_in[21];
    const float* bn_v   = (const float*)d_in[22];
    float* out = (float*)d_out;

    const int N = in_sizes[0] / IN_FEAT;     // 100000
    const int E = in_sizes[1] / 2;           // 1600000

    float *d_agg7, *d_cat, *d_pool, *d_hid;
    int *d_deg, *d_cursor, *d_rowstart, *d_esrc, *d_chunkoff;
    cudaGetSymbolAddress((void**)&d_agg7, g_agg7);
    cudaGetSymbolAddress((void**)&d_cat, g_cat);
    cudaGetSymbolAddress((void**)&d_pool, g_pool);
    cudaGetSymbolAddress((void**)&d_hid, g_hid);
    cudaGetSymbolAddress((void**)&d_deg, g_deg);
    cudaGetSymbolAddress((void**)&d_cursor, g_cursor);
    cudaGetSymbolAddress((void**)&d_rowstart, g_rowstart);
    cudaGetSymbolAddress((void**)&d_esrc, g_esrc);
    cudaGetSymbolAddress((void**)&d_chunkoff, g_chunkoff);

    const int* src = ei;
    const int* dst = ei + E;

    const int gemm_blocks = (N + 127) / 128;
    const int SMEM_GIN = (16384 + 2 * 2048) * 4;             // 81920
    const int SMEM_L0  = (128 * LDP + 1024 + 16 * LDP) * 4;  // 80128
    cudaFuncSetAttribute(fused_gin_kernel, cudaFuncAttributeMaxDynamicSharedMemorySize, SMEM_GIN);
    cudaFuncSetAttribute(fused_l0_kernel,  cudaFuncAttributeMaxDynamicSharedMemorySize, SMEM_L0);

    // ---- CSR-by-dst build ----
    cudaMemsetAsync(d_deg, 0, N * sizeof(int));
    hist_kernel<<<(E + 255) / 256, 256>>>(dst, d_deg, E);
    scan1_kernel<<<NCHUNK, 256>>>(d_deg, d_chunkoff, N);
    scan2_kernel<<<1, 32>>>(d_chunkoff, d_rowstart, NCHUNK, N);
    scan3_kernel<<<NCHUNK, 256>>>(d_deg, d_chunkoff, d_rowstart, d_cursor, N);
    fill_kernel<<<(E + 255) / 256, 256>>>(src, dst, d_cursor, d_esrc, E);

    // ---- layer 0 ----
    cudaMemsetAsync(d_agg7, 0, (size_t)N * 8 * sizeof(float));
    scatter7_kernel<<<(E + 255) / 256, 256>>>(x, src, dst, d_agg7, E);
    fused_l0_kernel<<<gemm_blocks, 256, SMEM_L0>>>(x, d_agg7, w1[0], b1[0],
                                                   w2[0], b2[0], d_cat, 3 * H, N);

    // ---- layers 1, 2: fully fused gather + MLP ----
    for (int l = 1; l < 3; l++) {
        const float* h_prev = d_cat + (size_t)(l - 1) * H;  // row stride 384
        fused_gin_kernel<<<gemm_blocks, 256, SMEM_GIN>>>(h_prev, 3 * H,
                                                         d_rowstart, d_esrc,
                                                         w1[l], b1[l], w2[l], b2[l],
                                                         d_cat + (size_t)l * H, 3 * H, N);
    }

    // ---- global add pool ----
    cudaMemsetAsync(d_pool, 0, (size_t)NUM_GRAPHS * 384 * sizeof(float));
    pool_kernel<<<(N * 96 + 255) / 256, 256>>>(d_cat, batch, d_pool, N);

    // ---- classifier ----
    clf1_kernel<<<NUM_GRAPHS, 256>>>(d_pool, clf_w1, clf_b1, bn_g, bn_b, bn_m, bn_v, d_hid);
    clf2_kernel<<<(NUM_GRAPHS * 2 + 255) / 256, 256>>>(d_hid, clf_w2, clf_b2, out);
}